// round 9
// baseline (speedup 1.0000x reference)
#include <cuda_runtime.h>
#include <cuda_bf16.h>

#define T_TOKENS 8192
#define D_DIM    768
#define N_EXP    8
#define CAP      2048

// Scratch (device allocation is forbidden)
__device__ int   g_expert_index[T_TOKENS];
__device__ float g_expert_gate[T_TOKENS];

// ---------------------------------------------------------------------------
// 1) Fused router + zero-fill.
//    Blocks 0..1023 (8 warps each) first route 8 tokens apiece:
//      logits = x[t] @ W  (768x8 dot), softmax top-1:
//      index = argmax(logits) (first max wins), gate = 1/sum(exp(l - lmax)).
//    Then ALL blocks join a grid-stride float4 streaming zero-fill of the
//    full 1 GiB output — the HBM-write roofline of the problem. The router
//    reads/FMAs hide under the store stream; grid-stride absorbs the skew.
// ---------------------------------------------------------------------------
__global__ void __launch_bounds__(256)
fill_route_kernel(const float* __restrict__ x,
                  const float* __restrict__ W,
                  float4* __restrict__ out, long long n4) {
    // --- router phase: first 1024 blocks, one warp per token ---
    if (blockIdx.x < T_TOKENS / 8) {
        int lane  = threadIdx.x & 31;
        int token = blockIdx.x * 8 + (threadIdx.x >> 5);

        const float* xr = x + (size_t)token * D_DIM;
        float acc[N_EXP];
#pragma unroll
        for (int e = 0; e < N_EXP; e++) acc[e] = 0.0f;

        // 768 = 32 lanes * 24 iters; x coalesced (128B/warp), W (24 KB) cached.
#pragma unroll 4
        for (int d = lane; d < D_DIM; d += 32) {
            float xv = __ldg(xr + d);
            const float* wr = W + (size_t)d * N_EXP;
#pragma unroll
            for (int e = 0; e < N_EXP; e++) acc[e] += xv * __ldg(wr + e);
        }

#pragma unroll
        for (int e = 0; e < N_EXP; e++) {
#pragma unroll
            for (int o = 16; o > 0; o >>= 1)
                acc[e] += __shfl_xor_sync(0xFFFFFFFFu, acc[e], o);
        }

        if (lane == 0) {
            float m = acc[0];
            int   mi = 0;
#pragma unroll
            for (int e = 1; e < N_EXP; e++) {
                if (acc[e] > m) { m = acc[e]; mi = e; }  // first max (jax top_k)
            }
            float s = 0.0f;
#pragma unroll
            for (int e = 0; e < N_EXP; e++) s += __expf(acc[e] - m);
            g_expert_index[token] = mi;
            g_expert_gate[token]  = 1.0f / s;
        }
    }

    // --- fill phase: everyone; 4x unrolled grid-stride streaming stores ---
    const float4 z = make_float4(0.f, 0.f, 0.f, 0.f);
    long long stride = (long long)gridDim.x * blockDim.x;
    long long i      = (long long)blockIdx.x * blockDim.x + threadIdx.x;
    for (; i + 3 * stride < n4; i += 4 * stride) {
        __stcs(&out[i],              z);
        __stcs(&out[i +     stride], z);
        __stcs(&out[i + 2 * stride], z);
        __stcs(&out[i + 3 * stride], z);
    }
    for (; i < n4; i += stride) __stcs(&out[i], z);
}

// ---------------------------------------------------------------------------
// 2) Fused scan + scatter. One block (1024 thr) per expert.
//    Inclusive 1-indexed rank of each token within its expert; kept iff
//    rank < 2048 (reference applies position_in_expert < C to the inclusive
//    rank: valid slots are 1..2047, slot 0 never used).
//    Kept token t (expert e, slot p) writes:
//      dispatch[t, e, p] = 1.0
//      combined[t, e, p] = gate[t]
//    Layout: out = [dispatch (T,E,C) | combined (T,E,C)], row-major.
// ---------------------------------------------------------------------------
__global__ void scan_scatter_kernel(float* __restrict__ out) {
    const int e    = blockIdx.x;
    const int tid  = threadIdx.x;
    const int lane = tid & 31;
    const int wid  = tid >> 5;

    __shared__ int warp_sums[32];
    __shared__ int s_carry;
    if (tid == 0) s_carry = 0;
    __syncthreads();

    for (int base = 0; base < T_TOKENS; base += 1024) {
        int t    = base + tid;
        int flag = (g_expert_index[t] == e) ? 1 : 0;

        // warp inclusive scan of membership flags
        int v = flag;
#pragma unroll
        for (int o = 1; o < 32; o <<= 1) {
            int n = __shfl_up_sync(0xFFFFFFFFu, v, o);
            if (lane >= o) v += n;
        }
        if (lane == 31) warp_sums[wid] = v;
        __syncthreads();

        if (tid < 32) {
            int w = warp_sums[tid];
#pragma unroll
            for (int o = 1; o < 32; o <<= 1) {
                int n = __shfl_up_sync(0xFFFFFFFFu, w, o);
                if (tid >= o) w += n;
            }
            warp_sums[tid] = w;
        }
        __syncthreads();

        int pref = (wid > 0) ? warp_sums[wid - 1] : 0;
        int p    = s_carry + pref + v;      // inclusive, 1-indexed

        if (flag && p < CAP) {
            size_t idx = (size_t)t * (N_EXP * CAP) + (size_t)e * CAP + (size_t)p;
            out[idx] = 1.0f;                                              // dispatch
            out[idx + (size_t)T_TOKENS * N_EXP * CAP] = g_expert_gate[t]; // combined
        }
        __syncthreads();

        if (tid == 0) s_carry += warp_sums[31];
        __syncthreads();
    }
}

// ---------------------------------------------------------------------------
extern "C" void kernel_launch(void* const* d_in, const int* in_sizes, int n_in,
                              void* d_out, int out_size) {
    const float* x = (const float*)d_in[0];   // (8192, 768) f32
    const float* W = (const float*)d_in[1];   // (768, 8) f32
    float* out = (float*)d_out;               // 2 * 8192*8*2048 f32

    fill_route_kernel<<<8192, 256>>>(x, W, (float4*)out, (long long)out_size / 4);
    scan_scatter_kernel<<<N_EXP, 1024>>>(out);
}